// round 13
// baseline (speedup 1.0000x reference)
#include <cuda_runtime.h>
#include <cuda_fp16.h>
#include <cstdint>

// DotInteraction: x [16384, 64, 128] fp32 -> upper-tri gram [16384, 2016] fp32.
// mma.sync m16n8k16 fp16 + ldmatrix (tcgen05 unavailable: harness targets sm_103 w/o 'a').
// Single-term fp16 gram (rel_err ~2.9e-4 < 1e-3, validated R11). Gram-symmetry frag
// aliasing: stripe s's A-frag regs {r0,r2}/{r1,r3} are the B-frags of cols 16s..+7/+8..+15.
// R13: grid-stride x2 only (halves wave count, decorrelates load phases). Scalar
// epilogue stores (R12's float2 trap: triangular rowoff has data-dependent parity,
// so pair stores are only 4B-aligned). 16KB smem -> 8 CTAs/SM.
// Block partition (16x16 blocks, upper 10):
//   w0: (0,0)(0,1)(1,1) stripes{0,1}   w1: (2,2)(2,3)(3,3) stripes{2,3}
//   w2: (0,2)(0,3)      stripes{0,2,3} w3: (1,2)(1,3)      stripes{1,2,3}
// Swizzle: byte(r, kc16) = (kc>>3)<<13 | r<<7 | (((kc&7)^(r&7))<<4)  [SW128 blocked atoms]

#define FF 64
#define NPAIR 2016
#define NITER 2

constexpr int MATB = 64 * 128 * 2;   // 16384 B: single fp16 matrix, swizzled
constexpr int SM_TOTAL = MATB;

__device__ __forceinline__ uint32_t smem_u32(const void* p) {
    uint32_t a;
    asm("{ .reg .u64 t; cvta.to.shared.u64 t, %1; cvt.u32.u64 %0, t; }" : "=r"(a) : "l"(p));
    return a;
}
__device__ __forceinline__ void ldsm_x4(uint32_t* r, uint32_t addr) {
    asm volatile("ldmatrix.sync.aligned.m8n8.x4.shared.b16 {%0,%1,%2,%3}, [%4];"
                 : "=r"(r[0]), "=r"(r[1]), "=r"(r[2]), "=r"(r[3]) : "r"(addr));
}
__device__ __forceinline__ void mma2(float* c, const uint32_t* a, uint32_t b0, uint32_t b1) {
    asm volatile(
        "mma.sync.aligned.m16n8k16.row.col.f32.f16.f16.f32 "
        "{%0,%1,%2,%3}, {%4,%5,%6,%7}, {%8,%9}, {%0,%1,%2,%3};"
        : "+f"(c[0]), "+f"(c[1]), "+f"(c[2]), "+f"(c[3])
        : "r"(a[0]), "r"(a[1]), "r"(a[2]), "r"(a[3]), "r"(b0), "r"(b1));
}
__device__ __forceinline__ uint32_t cvt_f16x2(float hi, float lo) {
    uint32_t r;
    asm("cvt.rn.f16x2.f32 %0, %1, %2;" : "=r"(r) : "f"(hi), "f"(lo));
    return r;
}

// Warp body: NS stripes (values S0..S2), NB blocks as (index-into-stripe-list) pairs.
template <int NS, int NB, int S0, int S1, int S2,
          int B0s, int B0c, int B1s, int B1c, int B2s, int B2c>
__device__ __forceinline__ void run_warp(uint32_t sb, float* __restrict__ ob, int lid) {
    const int stripes[3] = {S0, S1, S2};
    const int bs[3] = {B0s, B1s, B2s};
    const int bc[3] = {B0c, B1c, B2c};

    float acc[NB][8];
#pragma unroll
    for (int b = 0; b < NB; ++b)
#pragma unroll
        for (int e = 0; e < 8; ++e) acc[b][e] = 0.0f;

    const int hA = lid >> 4;
    const uint32_t mA4 = (uint32_t)(((lid & 7) ^ hA) << 4);
    const uint32_t base = sb + ((uint32_t)(lid & 15) << 7);

#pragma unroll
    for (int kk = 0; kk < 8; ++kk) {
        const uint32_t koff = (uint32_t)((kk >> 2) << 13);
        const uint32_t cx = ((uint32_t)(((2 * kk) & 7) << 4)) ^ mA4;

        uint32_t fh[NS][4];
#pragma unroll
        for (int s = 0; s < NS; ++s)
            ldsm_x4(fh[s], base + (uint32_t)(stripes[s] * 2048) + koff + cx);

#pragma unroll
        for (int b = 0; b < NB; ++b) {
            const int si = bs[b], ci = bc[b];
            mma2(acc[b] + 0, fh[si], fh[ci][0], fh[ci][2]);   // cols 16C..+7
            mma2(acc[b] + 4, fh[si], fh[ci][1], fh[ci][3]);   // cols 16C+8..+15
        }
    }

    // epilogue: thread t -> (row S*16 + t/4 (+8), col 16C + 8cc + 2(t%4) + d)
    const int rb0 = lid >> 2;
    const int cb0 = 2 * (lid & 3);
#pragma unroll
    for (int b = 0; b < NB; ++b) {
        const int S = stripes[bs[b]], C = stripes[bc[b]];
        const bool diag = (S == C);          // compile-time after unroll
        const int ib = S * 16 + rb0;
#pragma unroll
        for (int cc = 0; cc < 2; ++cc) {
            const int j0 = 16 * C + 8 * cc + cb0;
#pragma unroll
            for (int half = 0; half < 2; ++half) {
                const int i = ib + 8 * half;
                const int rowoff = i * (2 * FF - i - 1) / 2 - i - 1;  // out idx = rowoff + j
#pragma unroll
                for (int d = 0; d < 2; ++d) {
                    const int j = j0 + d;
                    if (!diag || j > i) ob[rowoff + j] = acc[b][4 * cc + 2 * half + d];
                }
            }
        }
    }
}

__global__ void __launch_bounds__(128, 8) dotint_mma_kernel(const float* __restrict__ x,
                                                            float* __restrict__ out) {
    extern __shared__ char smem[];
    const uint32_t sb = smem_u32(smem);
    const int tid = threadIdx.x;
    const int lid = tid & 31;
    const int wid = tid >> 5;

#pragma unroll
    for (int it = 0; it < NITER; ++it) {
        const int batch = blockIdx.x * NITER + it;
        if (it) __syncthreads();   // guard smem reuse across iterations

        // ---- load batch (2048 float4), convert fp32->fp16 packed, store swizzled ----
        const float4* xg = reinterpret_cast<const float4*>(x) + (size_t)batch * 2048;
#pragma unroll
        for (int l = 0; l < 16; ++l) {
            int idx = tid + l * 128;           // 0..2047
            int r = idx >> 5;                  // row 0..63
            int kc = (idx & 31) >> 1;          // 16B chunk 0..15
            int sub = (idx & 1) << 3;          // byte offset within chunk
            float4 v = xg[idx];

            uint32_t p0 = cvt_f16x2(v.y, v.x);
            uint32_t p1 = cvt_f16x2(v.w, v.z);

            uint32_t off = ((uint32_t)(kc >> 3) << 13) + ((uint32_t)r << 7) +
                           ((uint32_t)(((kc & 7) ^ (r & 7)) << 4)) + (uint32_t)sub;
            *reinterpret_cast<uint2*>(smem + off) = make_uint2(p0, p1);
        }
        __syncthreads();

        // ---- compute: symmetry-partitioned 16x16 blocks ----
        float* ob = out + (size_t)batch * NPAIR;
        switch (wid) {
            case 0:  // blocks (0,0) (0,1) (1,1); stripes {0,1}
                run_warp<2, 3, 0, 1, 0, 0, 0, 0, 1, 1, 1>(sb, ob, lid);
                break;
            case 1:  // blocks (2,2) (2,3) (3,3); stripes {2,3}
                run_warp<2, 3, 2, 3, 0, 0, 0, 0, 1, 1, 1>(sb, ob, lid);
                break;
            case 2:  // blocks (0,2) (0,3); stripes {0,2,3}
                run_warp<3, 2, 0, 2, 3, 0, 1, 0, 2, 0, 0>(sb, ob, lid);
                break;
            default: // blocks (1,2) (1,3); stripes {1,2,3}
                run_warp<3, 2, 1, 2, 3, 0, 1, 0, 2, 0, 0>(sb, ob, lid);
                break;
        }
    }
}

extern "C" void kernel_launch(void* const* d_in, const int* in_sizes, int n_in,
                              void* d_out, int out_size) {
    const float* x = (const float*)d_in[0];
    float* out = (float*)d_out;
    int nbatch = in_sizes[0] / (FF * 128);   // 16384
    cudaFuncSetAttribute(dotint_mma_kernel, cudaFuncAttributeMaxDynamicSharedMemorySize, SM_TOTAL);
    dotint_mma_kernel<<<nbatch / NITER, 128, SM_TOTAL>>>(x, out);
}

// round 14
// speedup vs baseline: 1.0066x; 1.0066x over previous
#include <cuda_runtime.h>
#include <cuda_fp16.h>
#include <cstdint>

// DotInteraction: x [16384, 64, 128] fp32 -> upper-tri gram [16384, 2016] fp32.
// mma.sync m16n8k16 fp16 + ldmatrix (tcgen05 unavailable: harness targets sm_103 w/o 'a').
// Single-term fp16 gram (rel_err ~2.9e-4 < 1e-3, validated R11). Gram-symmetry frag
// aliasing: stripe s's A-frag regs {r0,r2}/{r1,r3} are the B-frags of cols 16s..+7/+8..+15.
// R14: R11 structure (grid 16384, 16KB smem, 8 CTAs/SM) + streaming cache hints:
// __ldcs on read-once input, __stcs on write-once output (free L2 for write coalescing).
// Block partition (16x16 blocks, upper 10):
//   w0: (0,0)(0,1)(1,1) stripes{0,1}   w1: (2,2)(2,3)(3,3) stripes{2,3}
//   w2: (0,2)(0,3)      stripes{0,2,3} w3: (1,2)(1,3)      stripes{1,2,3}
// Swizzle: byte(r, kc16) = (kc>>3)<<13 | r<<7 | (((kc&7)^(r&7))<<4)  [SW128 blocked atoms]

#define FF 64
#define NPAIR 2016

constexpr int MATB = 64 * 128 * 2;   // 16384 B: single fp16 matrix, swizzled
constexpr int SM_TOTAL = MATB;

__device__ __forceinline__ uint32_t smem_u32(const void* p) {
    uint32_t a;
    asm("{ .reg .u64 t; cvta.to.shared.u64 t, %1; cvt.u32.u64 %0, t; }" : "=r"(a) : "l"(p));
    return a;
}
__device__ __forceinline__ void ldsm_x4(uint32_t* r, uint32_t addr) {
    asm volatile("ldmatrix.sync.aligned.m8n8.x4.shared.b16 {%0,%1,%2,%3}, [%4];"
                 : "=r"(r[0]), "=r"(r[1]), "=r"(r[2]), "=r"(r[3]) : "r"(addr));
}
__device__ __forceinline__ void mma2(float* c, const uint32_t* a, uint32_t b0, uint32_t b1) {
    asm volatile(
        "mma.sync.aligned.m16n8k16.row.col.f32.f16.f16.f32 "
        "{%0,%1,%2,%3}, {%4,%5,%6,%7}, {%8,%9}, {%0,%1,%2,%3};"
        : "+f"(c[0]), "+f"(c[1]), "+f"(c[2]), "+f"(c[3])
        : "r"(a[0]), "r"(a[1]), "r"(a[2]), "r"(a[3]), "r"(b0), "r"(b1));
}
__device__ __forceinline__ uint32_t cvt_f16x2(float hi, float lo) {
    uint32_t r;
    asm("cvt.rn.f16x2.f32 %0, %1, %2;" : "=r"(r) : "f"(hi), "f"(lo));
    return r;
}

// Warp body: NS stripes (values S0..S2), NB blocks as (index-into-stripe-list) pairs.
template <int NS, int NB, int S0, int S1, int S2,
          int B0s, int B0c, int B1s, int B1c, int B2s, int B2c>
__device__ __forceinline__ void run_warp(uint32_t sb, float* __restrict__ ob, int lid) {
    const int stripes[3] = {S0, S1, S2};
    const int bs[3] = {B0s, B1s, B2s};
    const int bc[3] = {B0c, B1c, B2c};

    float acc[NB][8];
#pragma unroll
    for (int b = 0; b < NB; ++b)
#pragma unroll
        for (int e = 0; e < 8; ++e) acc[b][e] = 0.0f;

    const int hA = lid >> 4;
    const uint32_t mA4 = (uint32_t)(((lid & 7) ^ hA) << 4);
    const uint32_t base = sb + ((uint32_t)(lid & 15) << 7);

#pragma unroll
    for (int kk = 0; kk < 8; ++kk) {
        const uint32_t koff = (uint32_t)((kk >> 2) << 13);
        const uint32_t cx = ((uint32_t)(((2 * kk) & 7) << 4)) ^ mA4;

        uint32_t fh[NS][4];
#pragma unroll
        for (int s = 0; s < NS; ++s)
            ldsm_x4(fh[s], base + (uint32_t)(stripes[s] * 2048) + koff + cx);

#pragma unroll
        for (int b = 0; b < NB; ++b) {
            const int si = bs[b], ci = bc[b];
            mma2(acc[b] + 0, fh[si], fh[ci][0], fh[ci][2]);   // cols 16C..+7
            mma2(acc[b] + 4, fh[si], fh[ci][1], fh[ci][3]);   // cols 16C+8..+15
        }
    }

    // epilogue: thread t -> (row S*16 + t/4 (+8), col 16C + 8cc + 2(t%4) + d)
    const int rb0 = lid >> 2;
    const int cb0 = 2 * (lid & 3);
#pragma unroll
    for (int b = 0; b < NB; ++b) {
        const int S = stripes[bs[b]], C = stripes[bc[b]];
        const bool diag = (S == C);          // compile-time after unroll
        const int ib = S * 16 + rb0;
#pragma unroll
        for (int cc = 0; cc < 2; ++cc) {
            const int j0 = 16 * C + 8 * cc + cb0;
#pragma unroll
            for (int half = 0; half < 2; ++half) {
                const int i = ib + 8 * half;
                const int rowoff = i * (2 * FF - i - 1) / 2 - i - 1;  // out idx = rowoff + j
#pragma unroll
                for (int d = 0; d < 2; ++d) {
                    const int j = j0 + d;
                    if (!diag || j > i)
                        __stcs(ob + rowoff + j, acc[b][4 * cc + 2 * half + d]);
                }
            }
        }
    }
}

__global__ void __launch_bounds__(128, 8) dotint_mma_kernel(const float* __restrict__ x,
                                                            float* __restrict__ out) {
    extern __shared__ char smem[];
    const uint32_t sb = smem_u32(smem);
    const int tid = threadIdx.x;
    const int lid = tid & 31;
    const int wid = tid >> 5;

    // ---- load batch (2048 float4, streaming), convert fp32->fp16 packed, store swizzled ----
    const float4* xg = reinterpret_cast<const float4*>(x) + (size_t)blockIdx.x * 2048;
#pragma unroll
    for (int it = 0; it < 16; ++it) {
        int idx = tid + it * 128;          // 0..2047
        int r = idx >> 5;                  // row 0..63
        int kc = (idx & 31) >> 1;          // 16B chunk 0..15
        int sub = (idx & 1) << 3;          // byte offset within chunk
        float4 v = __ldcs(xg + idx);

        uint32_t p0 = cvt_f16x2(v.y, v.x);
        uint32_t p1 = cvt_f16x2(v.w, v.z);

        uint32_t off = ((uint32_t)(kc >> 3) << 13) + ((uint32_t)r << 7) +
                       ((uint32_t)(((kc & 7) ^ (r & 7)) << 4)) + (uint32_t)sub;
        *reinterpret_cast<uint2*>(smem + off) = make_uint2(p0, p1);
    }
    __syncthreads();

    // ---- compute: symmetry-partitioned 16x16 blocks ----
    float* ob = out + (size_t)blockIdx.x * NPAIR;
    switch (wid) {
        case 0:  // blocks (0,0) (0,1) (1,1); stripes {0,1}
            run_warp<2, 3, 0, 1, 0, 0, 0, 0, 1, 1, 1>(sb, ob, lid);
            break;
        case 1:  // blocks (2,2) (2,3) (3,3); stripes {2,3}
            run_warp<2, 3, 2, 3, 0, 0, 0, 0, 1, 1, 1>(sb, ob, lid);
            break;
        case 2:  // blocks (0,2) (0,3); stripes {0,2,3}
            run_warp<3, 2, 0, 2, 3, 0, 1, 0, 2, 0, 0>(sb, ob, lid);
            break;
        default: // blocks (1,2) (1,3); stripes {1,2,3}
            run_warp<3, 2, 1, 2, 3, 0, 1, 0, 2, 0, 0>(sb, ob, lid);
            break;
    }
}

extern "C" void kernel_launch(void* const* d_in, const int* in_sizes, int n_in,
                              void* d_out, int out_size) {
    const float* x = (const float*)d_in[0];
    float* out = (float*)d_out;
    int nbatch = in_sizes[0] / (FF * 128);   // 16384
    cudaFuncSetAttribute(dotint_mma_kernel, cudaFuncAttributeMaxDynamicSharedMemorySize, SM_TOTAL);
    dotint_mma_kernel<<<nbatch, 128, SM_TOTAL>>>(x, out);
}

// round 15
// speedup vs baseline: 1.0222x; 1.0155x over previous
#include <cuda_runtime.h>
#include <cuda_fp16.h>
#include <cstdint>

// DotInteraction: x [16384, 64, 128] fp32 -> upper-tri gram [16384, 2016] fp32.
// mma.sync m16n8k16 fp16 + ldmatrix (tcgen05 unavailable: harness targets sm_103 w/o 'a').
// FINAL (= R11, best validated: 101.3us, rel_err 2.94e-4, DRAM 83% = traffic-minimal).
// Single-term fp16 gram: per-product residual <= 2*2^-12 -> global rel_err ~2.9e-4 < 1e-3.
// Gram-symmetry fragment aliasing: with k-major storage, stripe s's A-frag regs
// {r0,r2}/{r1,r3} ARE the B-frags of cols 16s..+7 / 16s+8..+15 -> B operands are free.
// 1 batch/CTA, 128 threads, 16KB smem -> 8 CTAs/SM (register-file-limited maximum).
// Block partition (16x16 blocks of the 64x64 gram, upper 10):
//   w0: (0,0)(0,1)(1,1) stripes{0,1}   w1: (2,2)(2,3)(3,3) stripes{2,3}
//   w2: (0,2)(0,3)      stripes{0,2,3} w3: (1,2)(1,3)      stripes{1,2,3}
// Swizzle: byte(r, kc16) = (kc>>3)<<13 | r<<7 | (((kc&7)^(r&7))<<4)  [SW128 blocked atoms]

#define FF 64
#define NPAIR 2016

constexpr int MATB = 64 * 128 * 2;   // 16384 B: single fp16 matrix, swizzled
constexpr int SM_TOTAL = MATB;

__device__ __forceinline__ uint32_t smem_u32(const void* p) {
    uint32_t a;
    asm("{ .reg .u64 t; cvta.to.shared.u64 t, %1; cvt.u32.u64 %0, t; }" : "=r"(a) : "l"(p));
    return a;
}
__device__ __forceinline__ void ldsm_x4(uint32_t* r, uint32_t addr) {
    asm volatile("ldmatrix.sync.aligned.m8n8.x4.shared.b16 {%0,%1,%2,%3}, [%4];"
                 : "=r"(r[0]), "=r"(r[1]), "=r"(r[2]), "=r"(r[3]) : "r"(addr));
}
__device__ __forceinline__ void mma2(float* c, const uint32_t* a, uint32_t b0, uint32_t b1) {
    asm volatile(
        "mma.sync.aligned.m16n8k16.row.col.f32.f16.f16.f32 "
        "{%0,%1,%2,%3}, {%4,%5,%6,%7}, {%8,%9}, {%0,%1,%2,%3};"
        : "+f"(c[0]), "+f"(c[1]), "+f"(c[2]), "+f"(c[3])
        : "r"(a[0]), "r"(a[1]), "r"(a[2]), "r"(a[3]), "r"(b0), "r"(b1));
}
__device__ __forceinline__ uint32_t cvt_f16x2(float hi, float lo) {
    uint32_t r;
    asm("cvt.rn.f16x2.f32 %0, %1, %2;" : "=r"(r) : "f"(hi), "f"(lo));
    return r;
}

// Warp body: NS stripes (values S0..S2), NB blocks as (index-into-stripe-list) pairs.
template <int NS, int NB, int S0, int S1, int S2,
          int B0s, int B0c, int B1s, int B1c, int B2s, int B2c>
__device__ __forceinline__ void run_warp(uint32_t sb, float* __restrict__ ob, int lid) {
    const int stripes[3] = {S0, S1, S2};
    const int bs[3] = {B0s, B1s, B2s};
    const int bc[3] = {B0c, B1c, B2c};

    float acc[NB][8];
#pragma unroll
    for (int b = 0; b < NB; ++b)
#pragma unroll
        for (int e = 0; e < 8; ++e) acc[b][e] = 0.0f;

    const int hA = lid >> 4;
    const uint32_t mA4 = (uint32_t)(((lid & 7) ^ hA) << 4);
    const uint32_t base = sb + ((uint32_t)(lid & 15) << 7);

#pragma unroll
    for (int kk = 0; kk < 8; ++kk) {
        const uint32_t koff = (uint32_t)((kk >> 2) << 13);
        const uint32_t cx = ((uint32_t)(((2 * kk) & 7) << 4)) ^ mA4;

        uint32_t fh[NS][4];
#pragma unroll
        for (int s = 0; s < NS; ++s)
            ldsm_x4(fh[s], base + (uint32_t)(stripes[s] * 2048) + koff + cx);

#pragma unroll
        for (int b = 0; b < NB; ++b) {
            const int si = bs[b], ci = bc[b];
            mma2(acc[b] + 0, fh[si], fh[ci][0], fh[ci][2]);   // cols 16C..+7
            mma2(acc[b] + 4, fh[si], fh[ci][1], fh[ci][3]);   // cols 16C+8..+15
        }
    }

    // epilogue: thread t -> (row S*16 + t/4 (+8), col 16C + 8cc + 2(t%4) + d)
    const int rb0 = lid >> 2;
    const int cb0 = 2 * (lid & 3);
#pragma unroll
    for (int b = 0; b < NB; ++b) {
        const int S = stripes[bs[b]], C = stripes[bc[b]];
        const bool diag = (S == C);          // compile-time after unroll
        const int ib = S * 16 + rb0;
#pragma unroll
        for (int cc = 0; cc < 2; ++cc) {
            const int j0 = 16 * C + 8 * cc + cb0;
#pragma unroll
            for (int half = 0; half < 2; ++half) {
                const int i = ib + 8 * half;
                const int rowoff = i * (2 * FF - i - 1) / 2 - i - 1;  // out idx = rowoff + j
#pragma unroll
                for (int d = 0; d < 2; ++d) {
                    const int j = j0 + d;
                    if (!diag || j > i) ob[rowoff + j] = acc[b][4 * cc + 2 * half + d];
                }
            }
        }
    }
}

__global__ void __launch_bounds__(128, 8) dotint_mma_kernel(const float* __restrict__ x,
                                                            float* __restrict__ out) {
    extern __shared__ char smem[];
    const uint32_t sb = smem_u32(smem);
    const int tid = threadIdx.x;
    const int lid = tid & 31;
    const int wid = tid >> 5;

    // ---- load batch (2048 float4), convert fp32->fp16 packed, store swizzled ----
    const float4* xg = reinterpret_cast<const float4*>(x) + (size_t)blockIdx.x * 2048;
#pragma unroll
    for (int it = 0; it < 16; ++it) {
        int idx = tid + it * 128;          // 0..2047
        int r = idx >> 5;                  // row 0..63
        int kc = (idx & 31) >> 1;          // 16B chunk 0..15
        int sub = (idx & 1) << 3;          // byte offset within chunk
        float4 v = xg[idx];

        uint32_t p0 = cvt_f16x2(v.y, v.x);
        uint32_t p1 = cvt_f16x2(v.w, v.z);

        uint32_t off = ((uint32_t)(kc >> 3) << 13) + ((uint32_t)r << 7) +
                       ((uint32_t)(((kc & 7) ^ (r & 7)) << 4)) + (uint32_t)sub;
        *reinterpret_cast<uint2*>(smem + off) = make_uint2(p0, p1);
    }
    __syncthreads();

    // ---- compute: symmetry-partitioned 16x16 blocks ----
    float* ob = out + (size_t)blockIdx.x * NPAIR;
    switch (wid) {
        case 0:  // blocks (0,0) (0,1) (1,1); stripes {0,1}
            run_warp<2, 3, 0, 1, 0, 0, 0, 0, 1, 1, 1>(sb, ob, lid);
            break;
        case 1:  // blocks (2,2) (2,3) (3,3); stripes {2,3}
            run_warp<2, 3, 2, 3, 0, 0, 0, 0, 1, 1, 1>(sb, ob, lid);
            break;
        case 2:  // blocks (0,2) (0,3); stripes {0,2,3}
            run_warp<3, 2, 0, 2, 3, 0, 1, 0, 2, 0, 0>(sb, ob, lid);
            break;
        default: // blocks (1,2) (1,3); stripes {1,2,3}
            run_warp<3, 2, 1, 2, 3, 0, 1, 0, 2, 0, 0>(sb, ob, lid);
            break;
    }
}

extern "C" void kernel_launch(void* const* d_in, const int* in_sizes, int n_in,
                              void* d_out, int out_size) {
    const float* x = (const float*)d_in[0];
    float* out = (float*)d_out;
    int nbatch = in_sizes[0] / (FF * 128);   // 16384
    cudaFuncSetAttribute(dotint_mma_kernel, cudaFuncAttributeMaxDynamicSharedMemorySize, SM_TOTAL);
    dotint_mma_kernel<<<nbatch, 128, SM_TOTAL>>>(x, out);
}